// round 9
// baseline (speedup 1.0000x reference)
#include <cuda_runtime.h>
#include <math.h>

#define BIGV   100000000.0f
#define GAMMA_ 0.05f
#define INVG_  20.0f
#define WARPP  256.0f
#define K_     4
#define B_     8
#define KB_    32
#define N_     800
#define C_     80
#define S_     128
#define Z_     32

// diagonal-major D: g_Dd[kb][d-2][n] = D[n][m], d-2 = n+m (0-indexed)
// rows padded to 1608 so 4-ahead prefetch never reads past the end
#define DDROWS_ 1608

// ---- scratch (device globals; no runtime allocation) ----
__device__ float g_sx[(size_t)KB_ * N_ * C_];   // sigmoid(mel_iters)
__device__ float g_sy[(size_t)B_  * N_ * C_];   // sigmoid(mel_targets)
__device__ float g_x2[KB_ * N_];                // row norms of sx
__device__ float g_y2[B_  * N_];                // row norms of sy
__device__ float g_Dd[(size_t)KB_ * DDROWS_ * N_];  // diagonal-major distances
__device__ float g_d [KB_];                     // DTW costs

// ============================================================
// Kernel 1: sigmoid + squared row norms. One warp per row.
// ============================================================
__global__ void prep_kernel(const float* __restrict__ mel_iters,
                            const float* __restrict__ mel_targets) {
    int wid  = (blockIdx.x * blockDim.x + threadIdx.x) >> 5;
    int lane = threadIdx.x & 31;
    const int xrows = KB_ * N_;
    const int total = xrows + B_ * N_;
    if (wid >= total) return;

    const float* src;
    float* dst;
    float* nrm;
    if (wid < xrows) {
        src = mel_iters + (size_t)wid * C_;
        dst = g_sx      + (size_t)wid * C_;
        nrm = g_x2 + wid;
    } else {
        int r = wid - xrows;
        src = mel_targets + (size_t)r * C_;
        dst = g_sy        + (size_t)r * C_;
        nrm = g_y2 + r;
    }
    float acc = 0.f;
    for (int c = lane; c < C_; c += 32) {
        float v = src[c];
        float s = 1.f / (1.f + expf(-v));
        dst[c] = s;
        acc += s * s;
    }
    #pragma unroll
    for (int o = 16; o; o >>= 1) acc += __shfl_xor_sync(0xffffffffu, acc, o);
    if (lane == 0) *nrm = acc;
}

// ============================================================
// Kernel 2: distance GEMM with diagonal-major epilogue.
// (identical to the 709us version)
// ============================================================
__global__ void __launch_bounds__(256) dist_gemm_kernel() {
    __shared__ float sA[80 * 65];
    __shared__ float sB[80 * 65];

    const int kb = blockIdx.z;
    const int b  = kb & 7;
    const int m0 = blockIdx.x * 64;
    const int n0 = blockIdx.y * 64;
    const int t  = threadIdx.x;

    const float* xbase = g_sx + (size_t)kb * N_ * C_ + (size_t)n0 * C_;
    const float* ybase = g_sy + (size_t)b  * N_ * C_ + (size_t)m0 * C_;

    for (int e = t; e < 64 * 80; e += 256) {
        int r = e / 80;
        int c = e - r * 80;
        float xv = (n0 + r < N_) ? xbase[r * C_ + c] : 0.f;
        float yv = (m0 + r < N_) ? ybase[r * C_ + c] : 0.f;
        sA[c * 65 + r] = xv;
        sB[c * 65 + r] = yv;
    }
    __syncthreads();

    const int tx = t & 15;
    const int ty = t >> 4;

    float acc[4][4];
    #pragma unroll
    for (int i = 0; i < 4; i++)
        #pragma unroll
        for (int j = 0; j < 4; j++) acc[i][j] = 0.f;

    #pragma unroll 8
    for (int k = 0; k < 80; k++) {
        float a[4], bb[4];
        #pragma unroll
        for (int i = 0; i < 4; i++) a[i]  = sA[k * 65 + ty * 4 + i];
        #pragma unroll
        for (int j = 0; j < 4; j++) bb[j] = sB[k * 65 + tx * 4 + j];
        #pragma unroll
        for (int i = 0; i < 4; i++)
            #pragma unroll
            for (int j = 0; j < 4; j++)
                acc[i][j] = fmaf(a[i], bb[j], acc[i][j]);
    }

    // ---- epilogue: D values -> smem tile (stride 66) ----
    __syncthreads();                 // all sA/sB reads done; alias sA as sD
    float* sD = sA;                  // needs 64*66 = 4224 <= 80*65 = 5200

    {
        int nb = ty * 4, mb = tx * 4;
        float xn[4], ym[4];
        #pragma unroll
        for (int ii = 0; ii < 4; ii++) {
            int n = n0 + nb + ii;
            int m = m0 + mb + ii;
            xn[ii] = g_x2[kb * N_ + (n < N_ ? n : N_ - 1)];
            ym[ii] = g_y2[b  * N_ + (m < N_ ? m : N_ - 1)];
        }
        #pragma unroll
        for (int ii = 0; ii < 4; ii++)
            #pragma unroll
            for (int jj = 0; jj < 4; jj++)
                sD[(nb + ii) * 66 + (mb + jj)] = xn[ii] + ym[jj] - 2.f * acc[ii][jj];
    }
    __syncthreads();

    // ---- write 127 local anti-diagonals, coalesced in n ----
    {
        const int w8   = t >> 5;
        const int lane = t & 31;
        float* DdBase = g_Dd + (size_t)kb * ((size_t)DDROWS_ * N_);
        for (int ld = w8; ld < 127; ld += 8) {
            int nlo = ld > 63 ? ld - 63 : 0;
            int nhi = ld < 63 ? ld : 63;
            for (int nl = nlo + lane; nl <= nhi; nl += 32) {
                int ml = ld - nl;
                int n = n0 + nl, m = m0 + ml;
                if (n < N_ && m < N_)
                    DdBase[(size_t)(n + m) * N_ + n] = sD[nl * 66 + ml];
            }
        }
    }
}

// ============================================================
// Kernel 3: soft-DTW wavefront, barrier-per-diagonal, RPT=2,
// TWO independent pairs per CTA (800 threads = 2 x 400). Each
// half-block runs the proven 709us algorithm on its own pair;
// one shared __syncthreads amortizes the per-diagonal barrier/
// latency cost across both pairs.
// ============================================================
#define NT2_   400
#define PAIRS_ 2

__device__ __forceinline__ float softmin3(float a, float bu, float c) {
    float m = fminf(a, fminf(bu, c));
    float d1 = a - m, d2 = bu - m, d3 = c - m;
    float second = d1 + d2 + d3 - fmaxf(d1, fmaxf(d2, d3));
    float sm = m;
    if (second < 1.0f) {
        sm = m - GAMMA_ * __logf(__expf(-d1 * INVG_) +
                                 __expf(-d2 * INVG_) +
                                 __expf(-d3 * INVG_));
    }
    return sm;
}

__global__ void __launch_bounds__(PAIRS_ * NT2_) dtw_kernel() {
    __shared__ float bnd[PAIRS_][2][NT2_];   // [pair][parity][t]

    const int tid = threadIdx.x;
    const int p   = tid / NT2_;              // pair within CTA (0/1)
    const int t   = tid - p * NT2_;          // local thread id
    const int kb  = blockIdx.x * PAIRS_ + p;
    const int i0  = 2 * t + 1;               // lower row (1-indexed)
    const int i1  = 2 * t + 2;               // upper row

    bnd[p][0][t] = BIGV;
    bnd[p][1][t] = BIGV;
    __syncthreads();

    float one0 = BIGV, one1 = BIGV, two0 = BIGV, two1 = BIGV;
    float b_one = BIGV;                      // row 2t @ d-1 (carried)

    // float2 view: row r (= d-2), element pair (2t, 2t+1) -> (.x=i0, .y=i1)
    const float2* Dd2 = (const float2*)g_Dd + (size_t)kb * ((size_t)DDROWS_ * (N_ / 2));

    // prefetch D for first 4 diagonals (rows 0..3)
    float2 cur0 = Dd2[(size_t)0 * (N_/2) + t];
    float2 cur1 = Dd2[(size_t)1 * (N_/2) + t];
    float2 cur2 = Dd2[(size_t)2 * (N_/2) + t];
    float2 cur3 = Dd2[(size_t)3 * (N_/2) + t];

    for (int d0 = 2; d0 <= 2 * N_; d0 += 4) {
        // prefetch next group: rows d0+2 .. d0+5  (max 1603 < DDROWS_)
        size_t rbase = (size_t)(d0 + 2) * (N_/2) + t;
        float2 nx0 = Dd2[rbase + 0 * (N_/2)];
        float2 nx1 = Dd2[rbase + 1 * (N_/2)];
        float2 nx2 = Dd2[rbase + 2 * (N_/2)];
        float2 nx3 = Dd2[rbase + 3 * (N_/2)];

        #pragma unroll
        for (int r = 0; r < 4; r++) {
            int d = d0 + r;
            if (d <= 2 * N_) {                       // block-uniform guard
                float b_one_new;
                if (t == 0) b_one_new = BIGV;                         // R[0][j>=1] = BIG
                else        b_one_new = bnd[p][(d - 1) & 1][t - 1];   // row 2t @ d-1
                float b_two = (t == 0) ? ((d == 2) ? 0.f : BIGV) : b_one;

                float2 Dv = (r == 0) ? cur0 : (r == 1) ? cur1 : (r == 2) ? cur2 : cur3;

                // cell (i0, j0)
                int j0 = d - i0;
                float new0 = BIGV;
                if (j0 >= 1 && j0 <= N_)
                    new0 = Dv.x + softmin3(b_two, b_one_new + WARPP, one0 + WARPP);

                // cell (i1, j1): all arms in-register
                int j1 = d - i1;
                float new1 = BIGV;
                if (j1 >= 1 && j1 <= N_)
                    new1 = Dv.y + softmin3(two0, one0 + WARPP, one1 + WARPP);

                two0 = one0; two1 = one1;
                one0 = new0; one1 = new1;
                b_one = b_one_new;

                bnd[p][d & 1][t] = new1;             // publish top row @ diag d
                __syncthreads();
            }
        }

        cur0 = nx0; cur1 = nx1; cur2 = nx2; cur3 = nx3;
    }

    // R[N][N] computed at d = 2N by local thread NT2_-1 of each pair
    if (t == NT2_ - 1) g_d[kb] = one1;
}

// ============================================================
// Kernel 4: finalize scalar losses (parallel, ~6.5us).
// ============================================================
__global__ void finalize_kernel(const int* __restrict__ mel_lens,
                                const int* __restrict__ src_lens,
                                const float* __restrict__ durations,
                                const float* __restrict__ mus,
                                const float* __restrict__ log_vars,
                                const int* __restrict__ step_p,
                                float* __restrict__ out) {
    __shared__ float s_kl[8];
    __shared__ float s_dur[B_];
    __shared__ float s_d[KB_];

    int t    = threadIdx.x;      // 256 threads
    int lane = t & 31;
    int w    = t >> 5;

    {
        float lv = log_vars[t];
        float mu = mus[t];
        float kl = 1.f + lv - mu * mu - expf(lv);
        #pragma unroll
        for (int o = 16; o; o >>= 1) kl += __shfl_xor_sync(0xffffffffu, kl, o);
        if (lane == 0) s_kl[w] = kl;
    }

    {
        float ds = durations[w * S_ + lane] + durations[w * S_ + 32 + lane]
                 + durations[w * S_ + 64 + lane] + durations[w * S_ + 96 + lane];
        #pragma unroll
        for (int o = 16; o; o >>= 1) ds += __shfl_xor_sync(0xffffffffu, ds, o);
        if (lane == 0) s_dur[w] = ds;
    }

    if (t < KB_) s_d[t] = g_d[t];
    __syncthreads();

    if (t == 0) {
        float klsum = 0.f;
        #pragma unroll
        for (int i = 0; i < 8; i++) klsum += s_kl[i];
        float kl_loss = -0.5f * klsum;

        float sum_d = 0.f;
        #pragma unroll
        for (int p = 0; p < KB_; p++) sum_d += s_d[p];
        float mel_iter_loss = sum_d / (float)B_;

        float mel = 0.f, durl = 0.f;
        #pragma unroll
        for (int b = 0; b < B_; b++) {
            float len = (float)mel_lens[b];
            mel += mel_iter_loss / ((float)K_ * len);
            durl += fabsf(s_dur[b] - len) / (float)src_lens[b];
        }
        mel  /= (float)B_;
        durl  = 2.f * durl / (float)B_;

        int step = step_p[0];
        float beta;
        if (step < 2000)       beta = 0.f;
        else if (step >= 8000) beta = 1.f;
        else                   beta = (float)(step - 2000) / 6000.f;

        float total = mel + durl + beta * kl_loss;
        out[0] = total;
        out[1] = mel;
        out[2] = durl;
        out[3] = kl_loss;
        out[4] = beta;
    }
}

// ============================================================
extern "C" void kernel_launch(void* const* d_in, const int* in_sizes, int n_in,
                              void* d_out, int out_size) {
    const float* mel_iters   = (const float*)d_in[0];
    const float* mel_targets = (const float*)d_in[1];
    const int*   mel_lens    = (const int*)  d_in[2];
    const int*   src_lens    = (const int*)  d_in[3];
    const float* durations   = (const float*)d_in[4];
    const float* mus         = (const float*)d_in[5];
    const float* log_vars    = (const float*)d_in[6];
    const int*   step        = (const int*)  d_in[7];
    float*       out         = (float*)d_out;

    (void)in_sizes; (void)n_in; (void)out_size;

    const int total_rows = KB_ * N_ + B_ * N_;
    const int wpb = 8;
    prep_kernel<<<(total_rows + wpb - 1) / wpb, wpb * 32>>>(mel_iters, mel_targets);

    dim3 g((N_ + 63) / 64, (N_ + 63) / 64, KB_);
    dist_gemm_kernel<<<g, 256>>>();

    dtw_kernel<<<KB_ / PAIRS_, PAIRS_ * NT2_>>>();

    finalize_kernel<<<1, 256>>>(mel_lens, src_lens, durations, mus, log_vars, step, out);
}

// round 10
// speedup vs baseline: 1.3737x; 1.3737x over previous
#include <cuda_runtime.h>
#include <math.h>

#define BIGV   100000000.0f
#define GAMMA_ 0.05f
#define INVG_  20.0f
#define WARPP  256.0f
#define K_     4
#define B_     8
#define KB_    32
#define N_     800
#define C_     80
#define S_     128
#define Z_     32

// diagonal-major D: g_Dd[kb][d-2][n] = D[n][m], d-2 = n+m (0-indexed)
#define DDROWS_ 1608

// ---- scratch (device globals; no runtime allocation) ----
__device__ float g_sx[(size_t)KB_ * N_ * C_];   // sigmoid(mel_iters)
__device__ float g_sy[(size_t)B_  * N_ * C_];   // sigmoid(mel_targets)
__device__ float g_x2[KB_ * N_];                // row norms of sx
__device__ float g_y2[B_  * N_];                // row norms of sy
__device__ float g_Dd[(size_t)KB_ * DDROWS_ * N_];  // diagonal-major distances
__device__ float g_d [KB_];                     // DTW costs

// ============================================================
// Kernel 1: sigmoid + squared row norms. One warp per row.
// ============================================================
__global__ void prep_kernel(const float* __restrict__ mel_iters,
                            const float* __restrict__ mel_targets) {
    int wid  = (blockIdx.x * blockDim.x + threadIdx.x) >> 5;
    int lane = threadIdx.x & 31;
    const int xrows = KB_ * N_;
    const int total = xrows + B_ * N_;
    if (wid >= total) return;

    const float* src;
    float* dst;
    float* nrm;
    if (wid < xrows) {
        src = mel_iters + (size_t)wid * C_;
        dst = g_sx      + (size_t)wid * C_;
        nrm = g_x2 + wid;
    } else {
        int r = wid - xrows;
        src = mel_targets + (size_t)r * C_;
        dst = g_sy        + (size_t)r * C_;
        nrm = g_y2 + r;
    }
    float acc = 0.f;
    for (int c = lane; c < C_; c += 32) {
        float v = src[c];
        float s = 1.f / (1.f + expf(-v));
        dst[c] = s;
        acc += s * s;
    }
    #pragma unroll
    for (int o = 16; o; o >>= 1) acc += __shfl_xor_sync(0xffffffffu, acc, o);
    if (lane == 0) *nrm = acc;
}

// ============================================================
// Kernel 2: distance GEMM with diagonal-major epilogue.
// (identical to the 709us version)
// ============================================================
__global__ void __launch_bounds__(256) dist_gemm_kernel() {
    __shared__ float sA[80 * 65];
    __shared__ float sB[80 * 65];

    const int kb = blockIdx.z;
    const int b  = kb & 7;
    const int m0 = blockIdx.x * 64;
    const int n0 = blockIdx.y * 64;
    const int t  = threadIdx.x;

    const float* xbase = g_sx + (size_t)kb * N_ * C_ + (size_t)n0 * C_;
    const float* ybase = g_sy + (size_t)b  * N_ * C_ + (size_t)m0 * C_;

    for (int e = t; e < 64 * 80; e += 256) {
        int r = e / 80;
        int c = e - r * 80;
        float xv = (n0 + r < N_) ? xbase[r * C_ + c] : 0.f;
        float yv = (m0 + r < N_) ? ybase[r * C_ + c] : 0.f;
        sA[c * 65 + r] = xv;
        sB[c * 65 + r] = yv;
    }
    __syncthreads();

    const int tx = t & 15;
    const int ty = t >> 4;

    float acc[4][4];
    #pragma unroll
    for (int i = 0; i < 4; i++)
        #pragma unroll
        for (int j = 0; j < 4; j++) acc[i][j] = 0.f;

    #pragma unroll 8
    for (int k = 0; k < 80; k++) {
        float a[4], bb[4];
        #pragma unroll
        for (int i = 0; i < 4; i++) a[i]  = sA[k * 65 + ty * 4 + i];
        #pragma unroll
        for (int j = 0; j < 4; j++) bb[j] = sB[k * 65 + tx * 4 + j];
        #pragma unroll
        for (int i = 0; i < 4; i++)
            #pragma unroll
            for (int j = 0; j < 4; j++)
                acc[i][j] = fmaf(a[i], bb[j], acc[i][j]);
    }

    // ---- epilogue: D values -> smem tile (stride 66) ----
    __syncthreads();
    float* sD = sA;

    {
        int nb = ty * 4, mb = tx * 4;
        float xn[4], ym[4];
        #pragma unroll
        for (int ii = 0; ii < 4; ii++) {
            int n = n0 + nb + ii;
            int m = m0 + mb + ii;
            xn[ii] = g_x2[kb * N_ + (n < N_ ? n : N_ - 1)];
            ym[ii] = g_y2[b  * N_ + (m < N_ ? m : N_ - 1)];
        }
        #pragma unroll
        for (int ii = 0; ii < 4; ii++)
            #pragma unroll
            for (int jj = 0; jj < 4; jj++)
                sD[(nb + ii) * 66 + (mb + jj)] = xn[ii] + ym[jj] - 2.f * acc[ii][jj];
    }
    __syncthreads();

    // ---- write 127 local anti-diagonals, coalesced in n ----
    {
        const int w8   = t >> 5;
        const int lane = t & 31;
        float* DdBase = g_Dd + (size_t)kb * ((size_t)DDROWS_ * N_);
        for (int ld = w8; ld < 127; ld += 8) {
            int nlo = ld > 63 ? ld - 63 : 0;
            int nhi = ld < 63 ? ld : 63;
            for (int nl = nlo + lane; nl <= nhi; nl += 32) {
                int ml = ld - nl;
                int n = n0 + nl, m = m0 + ml;
                if (n < N_ && m < N_)
                    DdBase[(size_t)(n + m) * N_ + n] = sD[nl * 66 + ml];
            }
        }
    }
}

// ============================================================
// Kernel 3: soft-DTW — epoch-skewed warp pipeline.
// 25 warps; warp w owns rows 32w+1..32w+32 (lane l -> row
// 32w+l+1). Time split into 74 epochs of E=32 diagonals; warp w
// runs window k = e - 2w (lag 2 epochs/warp, so the producer
// warp's boundary values are always 1+ epoch old). Intra-warp
// dependency via shfl_up; inter-warp boundary via a 128-slot
// smem ring written by lane 31 and preloaded ONCE per epoch
// into registers (broadcast by shfl during steps). One
// __syncthreads per epoch: 74 barriers instead of 1599.
// ============================================================
#define NWARP_  25
#define EW_     32
#define NWIN_   26     // windows per warp (26*32 = 832 >= 831 diags)
#define RINGSZ_ 128
#define RMASK_  (RINGSZ_ - 1)

__device__ __forceinline__ float softmin3(float a, float bu, float c) {
    float m = fminf(a, fminf(bu, c));
    float d1 = a - m, d2 = bu - m, d3 = c - m;
    float second = d1 + d2 + d3 - fmaxf(d1, fmaxf(d2, d3));
    float sm = m;
    if (second < 1.0f) {
        sm = m - GAMMA_ * __logf(__expf(-d1 * INVG_) +
                                 __expf(-d2 * INVG_) +
                                 __expf(-d3 * INVG_));
    }
    return sm;
}

__global__ void __launch_bounds__(NWARP_ * 32) dtw_kernel() {
    __shared__ float bnd[NWARP_][RINGSZ_];   // bnd[w][d & 127] = R[32w+32][d-(32w+32)]

    const int kb   = blockIdx.x;
    const int w    = threadIdx.x >> 5;
    const int lane = threadIdx.x & 31;
    const int i    = 32 * w + lane + 1;      // my row (1-indexed)
    const int dstart = 32 * w + 2;           // first diag of warp's window 0

    __syncthreads();                          // (bnd needs no init: reads only written slots)

    const float* DdCol = g_Dd + (size_t)kb * ((size_t)DDROWS_ * N_) + 32 * w + lane;
    const unsigned FULL = 0xffffffffu;

    float one_r = BIGV, two_r = BIGV;        // R[i][.] at diag d-1, d-2

    const int NEPOCH = 2 * (NWARP_ - 1) + NWIN_;   // 74
    for (int e = 0; e < NEPOCH; e++) {
        int k = e - 2 * w;
        if (k >= 0 && k < NWIN_) {
            const int A = dstart + EW_ * k;   // first diag of this window

            // ---- issue all 32 coalesced D loads (rows A-2 .. A+29, my col) ----
            float Dv[EW_];
            #pragma unroll
            for (int s = 0; s < EW_; s++)
                Dv[s] = __ldg(DdCol + (size_t)(A - 2 + s) * N_);

            // ---- preload producer boundary (diags A-2+lane and A+lane) ----
            float pre_a = BIGV, pre_b = BIGV;
            if (w > 0) {
                pre_a = bnd[w - 1][(A - 2 + lane) & RMASK_];
                pre_b = bnd[w - 1][(A + lane) & RMASK_];
            }

            #pragma unroll
            for (int s = 0; s < EW_; s++) {
                const int d = A + s;

                // boundary values for lane 0 (row 32w @ diag d-2, d-1)
                float b_two_v, b_one_v;
                if (s < 31) {
                    b_two_v = __shfl_sync(FULL, pre_a, s);
                    b_one_v = __shfl_sync(FULL, pre_a, s + 1);
                } else {
                    b_two_v = __shfl_sync(FULL, pre_a, 31);
                    b_one_v = __shfl_sync(FULL, pre_b, 30);
                }
                if (w == 0) {
                    b_one_v = BIGV;                       // R[0][j>=1] = BIG
                    b_two_v = (d == 2) ? 0.f : BIGV;      // R[0][0] = 0
                }

                float up_one = __shfl_up_sync(FULL, one_r, 1);
                float up_two = __shfl_up_sync(FULL, two_r, 1);
                if (lane == 0) { up_one = b_one_v; up_two = b_two_v; }

                int j = d - i;
                float rv = BIGV;
                if (j >= 1 && j <= N_)
                    rv = Dv[s] + softmin3(up_two, up_one + WARPP, one_r + WARPP);

                two_r = one_r;
                one_r = rv;

                if (lane == 31) {
                    bnd[w][d & RMASK_] = rv;              // publish top-row value
                    if (w == NWARP_ - 1 && d == 2 * N_)   // R[N][N]
                        g_d[kb] = rv;
                }
            }
        }
        __syncthreads();
    }
}

// ============================================================
// Kernel 4: finalize scalar losses (parallel, ~6.5us).
// ============================================================
__global__ void finalize_kernel(const int* __restrict__ mel_lens,
                                const int* __restrict__ src_lens,
                                const float* __restrict__ durations,
                                const float* __restrict__ mus,
                                const float* __restrict__ log_vars,
                                const int* __restrict__ step_p,
                                float* __restrict__ out) {
    __shared__ float s_kl[8];
    __shared__ float s_dur[B_];
    __shared__ float s_d[KB_];

    int t    = threadIdx.x;      // 256 threads
    int lane = t & 31;
    int w    = t >> 5;

    {
        float lv = log_vars[t];
        float mu = mus[t];
        float kl = 1.f + lv - mu * mu - expf(lv);
        #pragma unroll
        for (int o = 16; o; o >>= 1) kl += __shfl_xor_sync(0xffffffffu, kl, o);
        if (lane == 0) s_kl[w] = kl;
    }

    {
        float ds = durations[w * S_ + lane] + durations[w * S_ + 32 + lane]
                 + durations[w * S_ + 64 + lane] + durations[w * S_ + 96 + lane];
        #pragma unroll
        for (int o = 16; o; o >>= 1) ds += __shfl_xor_sync(0xffffffffu, ds, o);
        if (lane == 0) s_dur[w] = ds;
    }

    if (t < KB_) s_d[t] = g_d[t];
    __syncthreads();

    if (t == 0) {
        float klsum = 0.f;
        #pragma unroll
        for (int i = 0; i < 8; i++) klsum += s_kl[i];
        float kl_loss = -0.5f * klsum;

        float sum_d = 0.f;
        #pragma unroll
        for (int p = 0; p < KB_; p++) sum_d += s_d[p];
        float mel_iter_loss = sum_d / (float)B_;

        float mel = 0.f, durl = 0.f;
        #pragma unroll
        for (int b = 0; b < B_; b++) {
            float len = (float)mel_lens[b];
            mel += mel_iter_loss / ((float)K_ * len);
            durl += fabsf(s_dur[b] - len) / (float)src_lens[b];
        }
        mel  /= (float)B_;
        durl  = 2.f * durl / (float)B_;

        int step = step_p[0];
        float beta;
        if (step < 2000)       beta = 0.f;
        else if (step >= 8000) beta = 1.f;
        else                   beta = (float)(step - 2000) / 6000.f;

        float total = mel + durl + beta * kl_loss;
        out[0] = total;
        out[1] = mel;
        out[2] = durl;
        out[3] = kl_loss;
        out[4] = beta;
    }
}

// ============================================================
extern "C" void kernel_launch(void* const* d_in, const int* in_sizes, int n_in,
                              void* d_out, int out_size) {
    const float* mel_iters   = (const float*)d_in[0];
    const float* mel_targets = (const float*)d_in[1];
    const int*   mel_lens    = (const int*)  d_in[2];
    const int*   src_lens    = (const int*)  d_in[3];
    const float* durations   = (const float*)d_in[4];
    const float* mus         = (const float*)d_in[5];
    const float* log_vars    = (const float*)d_in[6];
    const int*   step        = (const int*)  d_in[7];
    float*       out         = (float*)d_out;

    (void)in_sizes; (void)n_in; (void)out_size;

    const int total_rows = KB_ * N_ + B_ * N_;
    const int wpb = 8;
    prep_kernel<<<(total_rows + wpb - 1) / wpb, wpb * 32>>>(mel_iters, mel_targets);

    dim3 g((N_ + 63) / 64, (N_ + 63) / 64, KB_);
    dist_gemm_kernel<<<g, 256>>>();

    dtw_kernel<<<KB_, NWARP_ * 32>>>();

    finalize_kernel<<<1, 256>>>(mel_lens, src_lens, durations, mus, log_vars, step, out);
}

// round 11
// speedup vs baseline: 1.3784x; 1.0034x over previous
#include <cuda_runtime.h>
#include <math.h>

#define BIGV   100000000.0f
#define GAMMA_ 0.05f
#define INVG_  20.0f
#define WARPP  256.0f
#define K_     4
#define B_     8
#define KB_    32
#define N_     800
#define C_     80
#define S_     128
#define Z_     32

// diagonal-major D: g_Dd[kb][d-2][n] = D[n][m], d-2 = n+m (0-indexed)
#define DDROWS_ 1608

// ---- scratch (device globals; no runtime allocation) ----
__device__ float g_sx[(size_t)KB_ * N_ * C_];   // sigmoid(mel_iters)
__device__ float g_sy[(size_t)B_  * N_ * C_];   // sigmoid(mel_targets)
__device__ float g_x2[KB_ * N_];                // row norms of sx
__device__ float g_y2[B_  * N_];                // row norms of sy
__device__ float g_Dd[(size_t)KB_ * DDROWS_ * N_];  // diagonal-major distances
__device__ float g_d [KB_];                     // DTW costs

// ============================================================
// Kernel 1: sigmoid + squared row norms. One warp per row.
// ============================================================
__global__ void prep_kernel(const float* __restrict__ mel_iters,
                            const float* __restrict__ mel_targets) {
    int wid  = (blockIdx.x * blockDim.x + threadIdx.x) >> 5;
    int lane = threadIdx.x & 31;
    const int xrows = KB_ * N_;
    const int total = xrows + B_ * N_;
    if (wid >= total) return;

    const float* src;
    float* dst;
    float* nrm;
    if (wid < xrows) {
        src = mel_iters + (size_t)wid * C_;
        dst = g_sx      + (size_t)wid * C_;
        nrm = g_x2 + wid;
    } else {
        int r = wid - xrows;
        src = mel_targets + (size_t)r * C_;
        dst = g_sy        + (size_t)r * C_;
        nrm = g_y2 + r;
    }
    float acc = 0.f;
    for (int c = lane; c < C_; c += 32) {
        float v = src[c];
        float s = 1.f / (1.f + expf(-v));
        dst[c] = s;
        acc += s * s;
    }
    #pragma unroll
    for (int o = 16; o; o >>= 1) acc += __shfl_xor_sync(0xffffffffu, acc, o);
    if (lane == 0) *nrm = acc;
}

// ============================================================
// Kernel 2: distance GEMM with diagonal-major epilogue.
// (identical to the 709/620us version)
// ============================================================
__global__ void __launch_bounds__(256) dist_gemm_kernel() {
    __shared__ float sA[80 * 65];
    __shared__ float sB[80 * 65];

    const int kb = blockIdx.z;
    const int b  = kb & 7;
    const int m0 = blockIdx.x * 64;
    const int n0 = blockIdx.y * 64;
    const int t  = threadIdx.x;

    const float* xbase = g_sx + (size_t)kb * N_ * C_ + (size_t)n0 * C_;
    const float* ybase = g_sy + (size_t)b  * N_ * C_ + (size_t)m0 * C_;

    for (int e = t; e < 64 * 80; e += 256) {
        int r = e / 80;
        int c = e - r * 80;
        float xv = (n0 + r < N_) ? xbase[r * C_ + c] : 0.f;
        float yv = (m0 + r < N_) ? ybase[r * C_ + c] : 0.f;
        sA[c * 65 + r] = xv;
        sB[c * 65 + r] = yv;
    }
    __syncthreads();

    const int tx = t & 15;
    const int ty = t >> 4;

    float acc[4][4];
    #pragma unroll
    for (int i = 0; i < 4; i++)
        #pragma unroll
        for (int j = 0; j < 4; j++) acc[i][j] = 0.f;

    #pragma unroll 8
    for (int k = 0; k < 80; k++) {
        float a[4], bb[4];
        #pragma unroll
        for (int i = 0; i < 4; i++) a[i]  = sA[k * 65 + ty * 4 + i];
        #pragma unroll
        for (int j = 0; j < 4; j++) bb[j] = sB[k * 65 + tx * 4 + j];
        #pragma unroll
        for (int i = 0; i < 4; i++)
            #pragma unroll
            for (int j = 0; j < 4; j++)
                acc[i][j] = fmaf(a[i], bb[j], acc[i][j]);
    }

    // ---- epilogue: D values -> smem tile (stride 66) ----
    __syncthreads();
    float* sD = sA;

    {
        int nb = ty * 4, mb = tx * 4;
        float xn[4], ym[4];
        #pragma unroll
        for (int ii = 0; ii < 4; ii++) {
            int n = n0 + nb + ii;
            int m = m0 + mb + ii;
            xn[ii] = g_x2[kb * N_ + (n < N_ ? n : N_ - 1)];
            ym[ii] = g_y2[b  * N_ + (m < N_ ? m : N_ - 1)];
        }
        #pragma unroll
        for (int ii = 0; ii < 4; ii++)
            #pragma unroll
            for (int jj = 0; jj < 4; jj++)
                sD[(nb + ii) * 66 + (mb + jj)] = xn[ii] + ym[jj] - 2.f * acc[ii][jj];
    }
    __syncthreads();

    // ---- write 127 local anti-diagonals, coalesced in n ----
    {
        const int w8   = t >> 5;
        const int lane = t & 31;
        float* DdBase = g_Dd + (size_t)kb * ((size_t)DDROWS_ * N_);
        for (int ld = w8; ld < 127; ld += 8) {
            int nlo = ld > 63 ? ld - 63 : 0;
            int nhi = ld < 63 ? ld : 63;
            for (int nl = nlo + lane; nl <= nhi; nl += 32) {
                int ml = ld - nl;
                int n = n0 + nl, m = m0 + ml;
                if (n < N_ && m < N_)
                    DdBase[(size_t)(n + m) * N_ + n] = sD[nl * 66 + ml];
            }
        }
    }
}

// ============================================================
// Kernel 3: soft-DTW — epoch-skewed warp pipeline (R10), with
// the 32-float D window buffer replaced by THREE 8-float groups
// in rotation (peak regs ~55 < 80 cap -> no local-memory spill).
// Groups 0,1 load at window start; group g+2 loads while group
// g is consumed (8-16 step prefetch distance hides DRAM).
// All arithmetic identical to R10.
// ============================================================
#define NWARP_  25
#define EW_     32
#define NWIN_   26
#define RINGSZ_ 128
#define RMASK_  (RINGSZ_ - 1)

__device__ __forceinline__ float softmin3(float a, float bu, float c) {
    float m = fminf(a, fminf(bu, c));
    float d1 = a - m, d2 = bu - m, d3 = c - m;
    float second = d1 + d2 + d3 - fmaxf(d1, fmaxf(d2, d3));
    float sm = m;
    if (second < 1.0f) {
        sm = m - GAMMA_ * __logf(__expf(-d1 * INVG_) +
                                 __expf(-d2 * INVG_) +
                                 __expf(-d3 * INVG_));
    }
    return sm;
}

__global__ void __launch_bounds__(NWARP_ * 32) dtw_kernel() {
    __shared__ float bnd[NWARP_][RINGSZ_];

    const int kb   = blockIdx.x;
    const int w    = threadIdx.x >> 5;
    const int lane = threadIdx.x & 31;
    const int i    = 32 * w + lane + 1;
    const int dstart = 32 * w + 2;

    __syncthreads();

    const float* DdCol = g_Dd + (size_t)kb * ((size_t)DDROWS_ * N_) + 32 * w + lane;
    const unsigned FULL = 0xffffffffu;

    float one_r = BIGV, two_r = BIGV;

    const int NEPOCH = 2 * (NWARP_ - 1) + NWIN_;   // 74
    for (int e = 0; e < NEPOCH; e++) {
        int k = e - 2 * w;
        if (k >= 0 && k < NWIN_) {
            const int A = dstart + EW_ * k;

            // preload producer boundary (diags A-2+lane and A+lane)
            float pre_a = BIGV, pre_b = BIGV;
            if (w > 0) {
                pre_a = bnd[w - 1][(A - 2 + lane) & RMASK_];
                pre_b = bnd[w - 1][(A + lane) & RMASK_];
            }

            // one DP step at diagonal d = A + s consuming D value Dval
            #define STEP(s_, Dval_) {                                           \
                const int d = A + (s_);                                         \
                float b_two_v, b_one_v;                                         \
                if ((s_) < 31) {                                                \
                    b_two_v = __shfl_sync(FULL, pre_a, (s_));                   \
                    b_one_v = __shfl_sync(FULL, pre_a, (s_) + 1);               \
                } else {                                                        \
                    b_two_v = __shfl_sync(FULL, pre_a, 31);                     \
                    b_one_v = __shfl_sync(FULL, pre_b, 30);                     \
                }                                                               \
                if (w == 0) {                                                   \
                    b_one_v = BIGV;                                             \
                    b_two_v = (d == 2) ? 0.f : BIGV;                            \
                }                                                               \
                float up_one = __shfl_up_sync(FULL, one_r, 1);                  \
                float up_two = __shfl_up_sync(FULL, two_r, 1);                  \
                if (lane == 0) { up_one = b_one_v; up_two = b_two_v; }          \
                int j = d - i;                                                  \
                float rv = BIGV;                                                \
                if (j >= 1 && j <= N_)                                          \
                    rv = (Dval_) + softmin3(up_two, up_one + WARPP,             \
                                            one_r + WARPP);                     \
                two_r = one_r;                                                  \
                one_r = rv;                                                     \
                if (lane == 31) {                                               \
                    bnd[w][d & RMASK_] = rv;                                    \
                    if (w == NWARP_ - 1 && d == 2 * N_) g_d[kb] = rv;           \
                }                                                               \
            }

            float bufA[8], bufB[8], bufC[8];
            // groups 0 (rows A-2..A+5) and 1 (rows A+6..A+13)
            #pragma unroll
            for (int q = 0; q < 8; q++) bufA[q] = __ldg(DdCol + (size_t)(A - 2 + q) * N_);
            #pragma unroll
            for (int q = 0; q < 8; q++) bufB[q] = __ldg(DdCol + (size_t)(A + 6 + q) * N_);

            // g=0: prefetch group 2, consume group 0
            #pragma unroll
            for (int q = 0; q < 8; q++) bufC[q] = __ldg(DdCol + (size_t)(A + 14 + q) * N_);
            #pragma unroll
            for (int q = 0; q < 8; q++) STEP(q, bufA[q]);

            // g=1: prefetch group 3 (into bufA), consume group 1
            #pragma unroll
            for (int q = 0; q < 8; q++) bufA[q] = __ldg(DdCol + (size_t)(A + 22 + q) * N_);
            #pragma unroll
            for (int q = 0; q < 8; q++) STEP(8 + q, bufB[q]);

            // g=2: consume group 2
            #pragma unroll
            for (int q = 0; q < 8; q++) STEP(16 + q, bufC[q]);

            // g=3: consume group 3
            #pragma unroll
            for (int q = 0; q < 8; q++) STEP(24 + q, bufA[q]);

            #undef STEP
        }
        __syncthreads();
    }
}

// ============================================================
// Kernel 4: finalize scalar losses (parallel, ~6.5us).
// ============================================================
__global__ void finalize_kernel(const int* __restrict__ mel_lens,
                                const int* __restrict__ src_lens,
                                const float* __restrict__ durations,
                                const float* __restrict__ mus,
                                const float* __restrict__ log_vars,
                                const int* __restrict__ step_p,
                                float* __restrict__ out) {
    __shared__ float s_kl[8];
    __shared__ float s_dur[B_];
    __shared__ float s_d[KB_];

    int t    = threadIdx.x;      // 256 threads
    int lane = t & 31;
    int w    = t >> 5;

    {
        float lv = log_vars[t];
        float mu = mus[t];
        float kl = 1.f + lv - mu * mu - expf(lv);
        #pragma unroll
        for (int o = 16; o; o >>= 1) kl += __shfl_xor_sync(0xffffffffu, kl, o);
        if (lane == 0) s_kl[w] = kl;
    }

    {
        float ds = durations[w * S_ + lane] + durations[w * S_ + 32 + lane]
                 + durations[w * S_ + 64 + lane] + durations[w * S_ + 96 + lane];
        #pragma unroll
        for (int o = 16; o; o >>= 1) ds += __shfl_xor_sync(0xffffffffu, ds, o);
        if (lane == 0) s_dur[w] = ds;
    }

    if (t < KB_) s_d[t] = g_d[t];
    __syncthreads();

    if (t == 0) {
        float klsum = 0.f;
        #pragma unroll
        for (int i = 0; i < 8; i++) klsum += s_kl[i];
        float kl_loss = -0.5f * klsum;

        float sum_d = 0.f;
        #pragma unroll
        for (int p = 0; p < KB_; p++) sum_d += s_d[p];
        float mel_iter_loss = sum_d / (float)B_;

        float mel = 0.f, durl = 0.f;
        #pragma unroll
        for (int b = 0; b < B_; b++) {
            float len = (float)mel_lens[b];
            mel += mel_iter_loss / ((float)K_ * len);
            durl += fabsf(s_dur[b] - len) / (float)src_lens[b];
        }
        mel  /= (float)B_;
        durl  = 2.f * durl / (float)B_;

        int step = step_p[0];
        float beta;
        if (step < 2000)       beta = 0.f;
        else if (step >= 8000) beta = 1.f;
        else                   beta = (float)(step - 2000) / 6000.f;

        float total = mel + durl + beta * kl_loss;
        out[0] = total;
        out[1] = mel;
        out[2] = durl;
        out[3] = kl_loss;
        out[4] = beta;
    }
}

// ============================================================
extern "C" void kernel_launch(void* const* d_in, const int* in_sizes, int n_in,
                              void* d_out, int out_size) {
    const float* mel_iters   = (const float*)d_in[0];
    const float* mel_targets = (const float*)d_in[1];
    const int*   mel_lens    = (const int*)  d_in[2];
    const int*   src_lens    = (const int*)  d_in[3];
    const float* durations   = (const float*)d_in[4];
    const float* mus         = (const float*)d_in[5];
    const float* log_vars    = (const float*)d_in[6];
    const int*   step        = (const int*)  d_in[7];
    float*       out         = (float*)d_out;

    (void)in_sizes; (void)n_in; (void)out_size;

    const int total_rows = KB_ * N_ + B_ * N_;
    const int wpb = 8;
    prep_kernel<<<(total_rows + wpb - 1) / wpb, wpb * 32>>>(mel_iters, mel_targets);

    dim3 g((N_ + 63) / 64, (N_ + 63) / 64, KB_);
    dist_gemm_kernel<<<g, 256>>>();

    dtw_kernel<<<KB_, NWARP_ * 32>>>();

    finalize_kernel<<<1, 256>>>(mel_lens, src_lens, durations, mus, log_vars, step, out);
}

// round 12
// speedup vs baseline: 1.3913x; 1.0093x over previous
#include <cuda_runtime.h>
#include <math.h>

#define BIGV   100000000.0f
#define GAMMA_ 0.05f
#define INVG_  20.0f
#define WARPP  256.0f
#define K_     4
#define B_     8
#define KB_    32
#define N_     800
#define C_     80
#define S_     128
#define Z_     32

// diagonal-major D: g_Dd[kb][d-2][n] = D[n][m], d-2 = n+m (0-indexed)
#define DDROWS_ 1608

// ---- scratch (device globals; no runtime allocation) ----
__device__ float g_sx[(size_t)KB_ * N_ * C_];   // sigmoid(mel_iters)
__device__ float g_sy[(size_t)B_  * N_ * C_];   // sigmoid(mel_targets)
__device__ float g_x2[KB_ * N_];                // row norms of sx
__device__ float g_y2[B_  * N_];                // row norms of sy
__device__ float g_Dd[(size_t)KB_ * DDROWS_ * N_];  // diagonal-major distances
__device__ float g_d [KB_];                     // DTW costs

// ============================================================
// Kernel 1: sigmoid + squared row norms. One warp per row.
// ============================================================
__global__ void prep_kernel(const float* __restrict__ mel_iters,
                            const float* __restrict__ mel_targets) {
    int wid  = (blockIdx.x * blockDim.x + threadIdx.x) >> 5;
    int lane = threadIdx.x & 31;
    const int xrows = KB_ * N_;
    const int total = xrows + B_ * N_;
    if (wid >= total) return;

    const float* src;
    float* dst;
    float* nrm;
    if (wid < xrows) {
        src = mel_iters + (size_t)wid * C_;
        dst = g_sx      + (size_t)wid * C_;
        nrm = g_x2 + wid;
    } else {
        int r = wid - xrows;
        src = mel_targets + (size_t)r * C_;
        dst = g_sy        + (size_t)r * C_;
        nrm = g_y2 + r;
    }
    float acc = 0.f;
    for (int c = lane; c < C_; c += 32) {
        float v = src[c];
        float s = 1.f / (1.f + expf(-v));
        dst[c] = s;
        acc += s * s;
    }
    #pragma unroll
    for (int o = 16; o; o >>= 1) acc += __shfl_xor_sync(0xffffffffu, acc, o);
    if (lane == 0) *nrm = acc;
}

// ============================================================
// Kernel 2: distance GEMM with diagonal-major epilogue.
// (identical to the 709/620/618us version)
// ============================================================
__global__ void __launch_bounds__(256) dist_gemm_kernel() {
    __shared__ float sA[80 * 65];
    __shared__ float sB[80 * 65];

    const int kb = blockIdx.z;
    const int b  = kb & 7;
    const int m0 = blockIdx.x * 64;
    const int n0 = blockIdx.y * 64;
    const int t  = threadIdx.x;

    const float* xbase = g_sx + (size_t)kb * N_ * C_ + (size_t)n0 * C_;
    const float* ybase = g_sy + (size_t)b  * N_ * C_ + (size_t)m0 * C_;

    for (int e = t; e < 64 * 80; e += 256) {
        int r = e / 80;
        int c = e - r * 80;
        float xv = (n0 + r < N_) ? xbase[r * C_ + c] : 0.f;
        float yv = (m0 + r < N_) ? ybase[r * C_ + c] : 0.f;
        sA[c * 65 + r] = xv;
        sB[c * 65 + r] = yv;
    }
    __syncthreads();

    const int tx = t & 15;
    const int ty = t >> 4;

    float acc[4][4];
    #pragma unroll
    for (int i = 0; i < 4; i++)
        #pragma unroll
        for (int j = 0; j < 4; j++) acc[i][j] = 0.f;

    #pragma unroll 8
    for (int k = 0; k < 80; k++) {
        float a[4], bb[4];
        #pragma unroll
        for (int i = 0; i < 4; i++) a[i]  = sA[k * 65 + ty * 4 + i];
        #pragma unroll
        for (int j = 0; j < 4; j++) bb[j] = sB[k * 65 + tx * 4 + j];
        #pragma unroll
        for (int i = 0; i < 4; i++)
            #pragma unroll
            for (int j = 0; j < 4; j++)
                acc[i][j] = fmaf(a[i], bb[j], acc[i][j]);
    }

    // ---- epilogue: D values -> smem tile (stride 66) ----
    __syncthreads();
    float* sD = sA;

    {
        int nb = ty * 4, mb = tx * 4;
        float xn[4], ym[4];
        #pragma unroll
        for (int ii = 0; ii < 4; ii++) {
            int n = n0 + nb + ii;
            int m = m0 + mb + ii;
            xn[ii] = g_x2[kb * N_ + (n < N_ ? n : N_ - 1)];
            ym[ii] = g_y2[b  * N_ + (m < N_ ? m : N_ - 1)];
        }
        #pragma unroll
        for (int ii = 0; ii < 4; ii++)
            #pragma unroll
            for (int jj = 0; jj < 4; jj++)
                sD[(nb + ii) * 66 + (mb + jj)] = xn[ii] + ym[jj] - 2.f * acc[ii][jj];
    }
    __syncthreads();

    // ---- write 127 local anti-diagonals, coalesced in n ----
    {
        const int w8   = t >> 5;
        const int lane = t & 31;
        float* DdBase = g_Dd + (size_t)kb * ((size_t)DDROWS_ * N_);
        for (int ld = w8; ld < 127; ld += 8) {
            int nlo = ld > 63 ? ld - 63 : 0;
            int nhi = ld < 63 ? ld : 63;
            for (int nl = nlo + lane; nl <= nhi; nl += 32) {
                int ml = ld - nl;
                int n = n0 + nl, m = m0 + ml;
                if (n < N_ && m < N_)
                    DdBase[(size_t)(n + m) * N_ + n] = sD[nl * 66 + ml];
            }
        }
    }
}

// ============================================================
// Kernel 3: soft-DTW — epoch-skewed warp pipeline, shfl-minimal.
// vs R11: per STEP only TWO shuffles (was four):
//   - up_two = previous step's up_one (register cache; lane 0's
//     cached post-override value IS the correct boundary, incl.
//     across window seams) -> shfl_up(two_r) and the b_two
//     broadcast are both deleted; two_r register eliminated.
//   - b_one broadcast has static index + loop-invariant operand
//     -> hoisted off the serial chain by the compiler.
// All arithmetic identical to R10/R11.
// ============================================================
#define NWARP_  25
#define EW_     32
#define NWIN_   26
#define RINGSZ_ 128
#define RMASK_  (RINGSZ_ - 1)

__device__ __forceinline__ float softmin3(float a, float bu, float c) {
    float m = fminf(a, fminf(bu, c));
    float d1 = a - m, d2 = bu - m, d3 = c - m;
    float second = d1 + d2 + d3 - fmaxf(d1, fmaxf(d2, d3));
    float sm = m;
    if (second < 1.0f) {
        sm = m - GAMMA_ * __logf(__expf(-d1 * INVG_) +
                                 __expf(-d2 * INVG_) +
                                 __expf(-d3 * INVG_));
    }
    return sm;
}

__global__ void __launch_bounds__(NWARP_ * 32) dtw_kernel() {
    __shared__ float bnd[NWARP_][RINGSZ_];

    const int kb   = blockIdx.x;
    const int w    = threadIdx.x >> 5;
    const int lane = threadIdx.x & 31;
    const int i    = 32 * w + lane + 1;
    const int dstart = 32 * w + 2;

    __syncthreads();

    const float* DdCol = g_Dd + (size_t)kb * ((size_t)DDROWS_ * N_) + 32 * w + lane;
    const unsigned FULL = 0xffffffffu;

    float one_r    = BIGV;   // R[i][.] at diag d-1
    float up_two_c = BIGV;   // cached shfl_up(two_r) == prev step's up_one

    const int NEPOCH = 2 * (NWARP_ - 1) + NWIN_;   // 74
    for (int e = 0; e < NEPOCH; e++) {
        int k = e - 2 * w;
        if (k >= 0 && k < NWIN_) {
            const int A = dstart + EW_ * k;

            // preload producer boundary (diags A-2+lane and A+lane)
            float pre_a = BIGV, pre_b = BIGV;
            if (w > 0) {
                pre_a = bnd[w - 1][(A - 2 + lane) & RMASK_];
                pre_b = bnd[w - 1][(A + lane) & RMASK_];
            }

            // first window: seed lane 0's cached boundary (diag A-2)
            if (k == 0) {
                float t0 = __shfl_sync(FULL, pre_a, 0);
                if (lane == 0) up_two_c = (w == 0) ? 0.f : t0;  // R[0][0]=0 at d=2
            }

            // one DP step at diagonal d = A + s consuming D value Dval
            #define STEP(s_, Dval_) {                                           \
                const int d = A + (s_);                                         \
                float b_one_v;                                                  \
                if ((s_) < 31) b_one_v = __shfl_sync(FULL, pre_a, (s_) + 1);    \
                else           b_one_v = __shfl_sync(FULL, pre_b, 30);          \
                if (w == 0) b_one_v = BIGV;                                     \
                float up_one = __shfl_up_sync(FULL, one_r, 1);                  \
                if (lane == 0) up_one = b_one_v;                                \
                int j = d - i;                                                  \
                float rv = BIGV;                                                \
                if (j >= 1 && j <= N_)                                          \
                    rv = (Dval_) + softmin3(up_two_c, up_one + WARPP,           \
                                            one_r + WARPP);                     \
                up_two_c = up_one;                                              \
                one_r = rv;                                                     \
                if (lane == 31) {                                               \
                    bnd[w][d & RMASK_] = rv;                                    \
                    if (w == NWARP_ - 1 && d == 2 * N_) g_d[kb] = rv;           \
                }                                                               \
            }

            float bufA[8], bufB[8], bufC[8];
            // groups 0 (rows A-2..A+5) and 1 (rows A+6..A+13)
            #pragma unroll
            for (int q = 0; q < 8; q++) bufA[q] = __ldg(DdCol + (size_t)(A - 2 + q) * N_);
            #pragma unroll
            for (int q = 0; q < 8; q++) bufB[q] = __ldg(DdCol + (size_t)(A + 6 + q) * N_);

            // g=0: prefetch group 2, consume group 0
            #pragma unroll
            for (int q = 0; q < 8; q++) bufC[q] = __ldg(DdCol + (size_t)(A + 14 + q) * N_);
            #pragma unroll
            for (int q = 0; q < 8; q++) STEP(q, bufA[q]);

            // g=1: prefetch group 3 (into bufA), consume group 1
            #pragma unroll
            for (int q = 0; q < 8; q++) bufA[q] = __ldg(DdCol + (size_t)(A + 22 + q) * N_);
            #pragma unroll
            for (int q = 0; q < 8; q++) STEP(8 + q, bufB[q]);

            // g=2: consume group 2
            #pragma unroll
            for (int q = 0; q < 8; q++) STEP(16 + q, bufC[q]);

            // g=3: consume group 3
            #pragma unroll
            for (int q = 0; q < 8; q++) STEP(24 + q, bufA[q]);

            #undef STEP
        }
        __syncthreads();
    }
}

// ============================================================
// Kernel 4: finalize scalar losses (parallel, ~6.5us).
// ============================================================
__global__ void finalize_kernel(const int* __restrict__ mel_lens,
                                const int* __restrict__ src_lens,
                                const float* __restrict__ durations,
                                const float* __restrict__ mus,
                                const float* __restrict__ log_vars,
                                const int* __restrict__ step_p,
                                float* __restrict__ out) {
    __shared__ float s_kl[8];
    __shared__ float s_dur[B_];
    __shared__ float s_d[KB_];

    int t    = threadIdx.x;      // 256 threads
    int lane = t & 31;
    int w    = t >> 5;

    {
        float lv = log_vars[t];
        float mu = mus[t];
        float kl = 1.f + lv - mu * mu - expf(lv);
        #pragma unroll
        for (int o = 16; o; o >>= 1) kl += __shfl_xor_sync(0xffffffffu, kl, o);
        if (lane == 0) s_kl[w] = kl;
    }

    {
        float ds = durations[w * S_ + lane] + durations[w * S_ + 32 + lane]
                 + durations[w * S_ + 64 + lane] + durations[w * S_ + 96 + lane];
        #pragma unroll
        for (int o = 16; o; o >>= 1) ds += __shfl_xor_sync(0xffffffffu, ds, o);
        if (lane == 0) s_dur[w] = ds;
    }

    if (t < KB_) s_d[t] = g_d[t];
    __syncthreads();

    if (t == 0) {
        float klsum = 0.f;
        #pragma unroll
        for (int i = 0; i < 8; i++) klsum += s_kl[i];
        float kl_loss = -0.5f * klsum;

        float sum_d = 0.f;
        #pragma unroll
        for (int p = 0; p < KB_; p++) sum_d += s_d[p];
        float mel_iter_loss = sum_d / (float)B_;

        float mel = 0.f, durl = 0.f;
        #pragma unroll
        for (int b = 0; b < B_; b++) {
            float len = (float)mel_lens[b];
            mel += mel_iter_loss / ((float)K_ * len);
            durl += fabsf(s_dur[b] - len) / (float)src_lens[b];
        }
        mel  /= (float)B_;
        durl  = 2.f * durl / (float)B_;

        int step = step_p[0];
        float beta;
        if (step < 2000)       beta = 0.f;
        else if (step >= 8000) beta = 1.f;
        else                   beta = (float)(step - 2000) / 6000.f;

        float total = mel + durl + beta * kl_loss;
        out[0] = total;
        out[1] = mel;
        out[2] = durl;
        out[3] = kl_loss;
        out[4] = beta;
    }
}

// ============================================================
extern "C" void kernel_launch(void* const* d_in, const int* in_sizes, int n_in,
                              void* d_out, int out_size) {
    const float* mel_iters   = (const float*)d_in[0];
    const float* mel_targets = (const float*)d_in[1];
    const int*   mel_lens    = (const int*)  d_in[2];
    const int*   src_lens    = (const int*)  d_in[3];
    const float* durations   = (const float*)d_in[4];
    const float* mus         = (const float*)d_in[5];
    const float* log_vars    = (const float*)d_in[6];
    const int*   step        = (const int*)  d_in[7];
    float*       out         = (float*)d_out;

    (void)in_sizes; (void)n_in; (void)out_size;

    const int total_rows = KB_ * N_ + B_ * N_;
    const int wpb = 8;
    prep_kernel<<<(total_rows + wpb - 1) / wpb, wpb * 32>>>(mel_iters, mel_targets);

    dim3 g((N_ + 63) / 64, (N_ + 63) / 64, KB_);
    dist_gemm_kernel<<<g, 256>>>();

    dtw_kernel<<<KB_, NWARP_ * 32>>>();

    finalize_kernel<<<1, 256>>>(mel_lens, src_lens, durations, mus, log_vars, step, out);
}